// round 7
// baseline (speedup 1.0000x reference)
#include <cuda_runtime.h>
#include <cstdint>

// Problem constants (B=1024, T=4096, N=2048, K=16, M=2^16)
#define T_DIM   4096
#define N_DIM   2048
#define K_DIM   16
#define THREADS 512
#define NPT     (N_DIM / THREADS)   // 4 neurons per thread, strided by 512
#define KP      (K_DIM / 2)         // 8 packed connection words per neuron

// Packed transposed connections: conn_P[k2][n] = c_{2k2}(lo16) | c_{2k2+1}(hi16).
// Indices are < 4096 so they fit in 12 bits. 64 KB, L1/L2-resident.
__device__ unsigned conn_P[KP * N_DIM];

__global__ void pack_conn_kernel(const int* __restrict__ conn) {
    int idx = blockIdx.x * blockDim.x + threadIdx.x;   // 0 .. N*KP-1
    if (idx < N_DIM * KP) {
        int n  = idx >> 3;      // idx / KP
        int k2 = idx & 7;       // idx % KP
        unsigned c0 = (unsigned)conn[n * K_DIM + 2 * k2];
        unsigned c1 = (unsigned)conn[n * K_DIM + 2 * k2 + 1];
        conn_P[k2 * N_DIM + n] = (c0 & 0xFFFFu) | (c1 << 16);
    }
}

__device__ __forceinline__ int ldcg_i32(const int* p) {
    int v;
    asm volatile("ld.global.cg.b32 %0, [%1];" : "=r"(v) : "l"(p));
    return v;
}

__device__ __forceinline__ void stcg_f32(float* p, float v) {
    asm volatile("st.global.cg.f32 [%0], %1;" :: "l"(p), "f"(v));
}

__global__ __launch_bounds__(THREADS)
void ram_layer_kernel(const int*  __restrict__ input_bits,   // [B, T]
                      const int*  __restrict__ memory,       // [N, M]
                      float*      __restrict__ out)          // [B, N] float32
{
    __shared__ unsigned bits[T_DIM / 32];   // 4096-bit set, 512 B

    const int b   = blockIdx.x;
    const int tid = threadIdx.x;

    // ---- Pack this batch row's bits into a shared bitset (coalesced+ballot) ----
    const int* row = input_bits + (size_t)b * T_DIM;
#pragma unroll
    for (int j = 0; j < T_DIM / THREADS; ++j) {
        int p = j * THREADS + tid;
        unsigned w = __ballot_sync(0xFFFFFFFFu, row[p] != 0);
        if ((tid & 31) == 0) bits[p >> 5] = w;
    }
    __syncthreads();

    // ---- Interleaved: build addr_j, immediately launch gather_j ----
    // Packed conn halves the build instruction count; each gather is issued
    // as soon as its address is ready so misses stack up across the loop.
    int vals[NPT];
#pragma unroll
    for (int j = 0; j < NPT; ++j) {
        const int n = j * THREADS + tid;                 // neuron-per-lane: coalesced
        unsigned a = 0;
#pragma unroll
        for (int k2 = 0; k2 < KP; ++k2) {
            unsigned pc = __ldg(&conn_P[k2 * N_DIM + n]);   // 128B coalesced, L1-hot
            unsigned c0 = pc & 0xFFFFu;
            unsigned c1 = pc >> 16;
            a |= ((bits[c0 >> 5] >> (c0 & 31)) & 1u) << (2 * k2);
            a |= ((bits[c1 >> 5] >> (c1 & 31)) & 1u) << (2 * k2 + 1);
        }
        vals[j] = ldcg_i32(memory + (((size_t)n) << 16) + a);  // L2-only random gather
    }

    // ---- Coalesced float stores (L2 write, no L1 allocate) ----
#pragma unroll
    for (int j = 0; j < NPT; ++j) {
        stcg_f32(out + (size_t)b * N_DIM + j * THREADS + tid,
                 (float)(vals[j] & 1));
    }
}

extern "C" void kernel_launch(void* const* d_in, const int* in_sizes, int n_in,
                              void* d_out, int out_size) {
    // Identify inputs by unique element counts (robust to metadata order):
    //   input_bits : B*T = 4,194,304   connections: N*K = 32,768
    //   memory     : N*M = 134,217,728
    const int* input_bits  = nullptr;
    const int* connections = nullptr;
    const int* memory      = nullptr;
    long long sz_bits = 0;

    for (int i = 0; i < n_in; ++i) {
        long long s = in_sizes[i];
        if (s == (long long)N_DIM * K_DIM) {
            connections = (const int*)d_in[i];
        } else if (s == (long long)N_DIM * 65536LL) {
            memory = (const int*)d_in[i];
        } else {
            input_bits = (const int*)d_in[i];
            sz_bits = s;
        }
    }

    // 32B L2 fetch granularity: measured to cut gather DRAM traffic 248->88MB.
    // Set only when not capturing (state persists into graph replays).
    cudaStreamCaptureStatus cap = cudaStreamCaptureStatusNone;
    cudaStreamIsCapturing((cudaStream_t)0, &cap);
    if (cap == cudaStreamCaptureStatusNone) {
        cudaDeviceSetLimit(cudaLimitMaxL2FetchGranularity, 32);
        cudaGetLastError();
    }

    const int B = (int)(sz_bits / T_DIM);   // 1024

    pack_conn_kernel<<<(N_DIM * KP + 255) / 256, 256>>>(connections);
    ram_layer_kernel<<<B, THREADS>>>(input_bits, memory, (float*)d_out);
}